// round 4
// baseline (speedup 1.0000x reference)
#include <cuda_runtime.h>

#define BB 16
#define TMAX 512
#define DD 512
#define T_FRAMES 4096   // TMAX * MAX_DUR(8)

// frame -> token index table (-1 = no token covers this frame)
__device__ int g_tok[BB * T_FRAMES];

// Kernel 1: per-batch cumsum of durations + scatter token index per frame.
// One block per batch, TMAX threads.
// NOTE: ds is int32 — JAX x64 is disabled by default, so the reference's
// astype(jnp.int64) actually produces int32 on the wire.
__global__ void build_tok_kernel(const int* __restrict__ ds) {
    const int b = blockIdx.x;
    const int t = threadIdx.x;
    __shared__ int s[TMAX];

    const int d = ds[b * TMAX + t];
    s[t] = d;
    __syncthreads();

    // Hillis-Steele inclusive scan over TMAX=512
    #pragma unroll
    for (int off = 1; off < TMAX; off <<= 1) {
        int v = (t >= off) ? s[t - off] : 0;
        __syncthreads();
        s[t] += v;
        __syncthreads();
    }
    const int end   = s[t];
    const int start = end - d;

    // init this batch's frame table to -1 (4096 entries / 512 threads = 8 each)
    #pragma unroll
    for (int i = 0; i < T_FRAMES / TMAX; i++) {
        g_tok[b * T_FRAMES + i * TMAX + t] = -1;
    }
    __syncthreads();   // orders the -1 fill before the scatter (block-scope)

    for (int f = start; f < end; f++) {
        g_tok[b * T_FRAMES + f] = t;
    }
}

// Kernel 2: one block per (b, frame) row. 128 threads, each writes one float4
// of ys (DD=512 floats) and one float4 of map (TMAX=512 floats).
__global__ void __launch_bounds__(128) scatter_kernel(
    const float4* __restrict__ xs,   // [B, TMAX, D/4]
    float4* __restrict__ ys,         // [B, T_FRAMES, D/4]
    float4* __restrict__ mp)         // [B, T_FRAMES, TMAX/4]
{
    const int row = blockIdx.x;            // b * T_FRAMES + f
    const int b   = row >> 12;             // / T_FRAMES
    const int i   = threadIdx.x;           // 0..127

    // All lanes read the same word: single-line L1 broadcast, no barrier.
    const int tok = __ldg(&g_tok[row]);

    float4 yv = make_float4(0.f, 0.f, 0.f, 0.f);
    if (tok >= 0) {
        yv = xs[((size_t)b * TMAX + tok) * (DD / 4) + i];
    }
    ys[(size_t)row * (DD / 4) + i] = yv;

    float4 mv = make_float4(0.f, 0.f, 0.f, 0.f);
    if (tok >= 0 && (tok >> 2) == i) {
        ((float*)&mv)[tok & 3] = 1.0f;
    }
    mp[(size_t)row * (TMAX / 4) + i] = mv;
}

extern "C" void kernel_launch(void* const* d_in, const int* in_sizes, int n_in,
                              void* d_out, int out_size) {
    const float* xs = (const float*)d_in[0];
    const int*   ds = (const int*)d_in[1];   // int32 (JAX x64 disabled)

    float* out = (float*)d_out;
    float* ys  = out;                                    // [B, T_FRAMES, D]
    float* mp  = out + (size_t)BB * T_FRAMES * DD;       // [B, T_FRAMES, TMAX]

    build_tok_kernel<<<BB, TMAX>>>(ds);
    scatter_kernel<<<BB * T_FRAMES, 128>>>(
        (const float4*)xs, (float4*)ys, (float4*)mp);
}

// round 5
// speedup vs baseline: 1.0352x; 1.0352x over previous
#include <cuda_runtime.h>

#define BB 16
#define TMAX 512
#define DD 512
#define T_FRAMES 4096   // TMAX * MAX_DUR(8)
#define RPB 4           // rows (frames) per block in the scatter kernel

// frame -> token index table (-1 = no token covers this frame)
__device__ int g_tok[BB * T_FRAMES];

// Kernel 1: per-batch cumsum of durations + scatter token index per frame.
// One block per batch, TMAX threads. ds is int32 (JAX x64 disabled).
__global__ void build_tok_kernel(const int* __restrict__ ds) {
    const int b = blockIdx.x;
    const int t = threadIdx.x;
    __shared__ int s[TMAX];

    const int d = ds[b * TMAX + t];
    s[t] = d;
    __syncthreads();

    // Hillis-Steele inclusive scan over TMAX=512
    #pragma unroll
    for (int off = 1; off < TMAX; off <<= 1) {
        int v = (t >= off) ? s[t - off] : 0;
        __syncthreads();
        s[t] += v;
        __syncthreads();
    }
    const int end   = s[t];
    const int start = end - d;

    // init this batch's frame table to -1 (4096 entries / 512 threads = 8 each)
    #pragma unroll
    for (int i = 0; i < T_FRAMES / TMAX; i++) {
        g_tok[b * T_FRAMES + i * TMAX + t] = -1;
    }
    __syncthreads();   // orders the -1 fill before the scatter (block-scope)

    for (int f = start; f < end; f++) {
        g_tok[b * T_FRAMES + f] = t;
    }
}

// Kernel 2: one block per RPB consecutive (b, frame) rows. 128 threads.
// Front-batched independent loads (MLP=RPB) then batched stores.
__global__ void __launch_bounds__(128) scatter_kernel(
    const float4* __restrict__ xs,   // [B, TMAX, D/4]
    float4* __restrict__ ys,         // [B, T_FRAMES, D/4]
    float4* __restrict__ mp)         // [B, T_FRAMES, TMAX/4]
{
    const int row0 = blockIdx.x * RPB;     // first of RPB consecutive rows
    const int b    = row0 >> 12;           // RPB | T_FRAMES -> same b for all
    const int i    = threadIdx.x;          // 0..127

    // Batch 1: token indices (same word across lanes -> L1 broadcast)
    int tok[RPB];
    #pragma unroll
    for (int j = 0; j < RPB; j++)
        tok[j] = __ldg(&g_tok[row0 + j]);

    // Batch 2: xs rows (independent LDG.128s; usually same line across j)
    float4 yv[RPB];
    #pragma unroll
    for (int j = 0; j < RPB; j++) {
        yv[j] = make_float4(0.f, 0.f, 0.f, 0.f);
        if (tok[j] >= 0)
            yv[j] = xs[((size_t)b * TMAX + tok[j]) * (DD / 4) + i];
    }

    // Batch 3: stores
    #pragma unroll
    for (int j = 0; j < RPB; j++)
        ys[(size_t)(row0 + j) * (DD / 4) + i] = yv[j];

    #pragma unroll
    for (int j = 0; j < RPB; j++) {
        float4 mv = make_float4(0.f, 0.f, 0.f, 0.f);
        if (tok[j] >= 0 && (tok[j] >> 2) == i)
            ((float*)&mv)[tok[j] & 3] = 1.0f;
        mp[(size_t)(row0 + j) * (TMAX / 4) + i] = mv;
    }
}

extern "C" void kernel_launch(void* const* d_in, const int* in_sizes, int n_in,
                              void* d_out, int out_size) {
    const float* xs = (const float*)d_in[0];
    const int*   ds = (const int*)d_in[1];   // int32 (JAX x64 disabled)

    float* out = (float*)d_out;
    float* ys  = out;                                    // [B, T_FRAMES, D]
    float* mp  = out + (size_t)BB * T_FRAMES * DD;       // [B, T_FRAMES, TMAX]

    build_tok_kernel<<<BB, TMAX>>>(ds);
    scatter_kernel<<<(BB * T_FRAMES) / RPB, 128>>>(
        (const float4*)xs, (float4*)ys, (float4*)mp);
}